// round 14
// baseline (speedup 1.0000x reference)
#include <cuda_runtime.h>
#include <math.h>
#include <stdint.h>

#define NNODES 50000
#define NEDG   400000
#define ETOT   450000
#define WID    256
#define NG     256
#define NPAD   50048        // 391 * 128
#define MTILES 391
#define DCAPW  64           // per-node degree cap for warp fast path

// ---------------- scratch globals ----------------
__device__ float g_h[(size_t)NNODES * WID];
__device__ float g_als[NNODES * 4];
__device__ float g_ald[NNODES * 4];
__device__ float g_esc[(size_t)ETOT * 4];    // fallback only (deg > DCAPW)
__device__ int   g_dst[ETOT];
__device__ int   g_srcE[ETOT];
__device__ int   g_scsr[ETOT];
__device__ int   g_deg[NNODES];
__device__ int   g_rowptr[NNODES + 1];
__device__ int   g_cursor[NNODES];
__device__ int   g_i64flag;
__device__ int   g_incl[NNODES];
__device__ int   g_bsum[64];
__device__ int   g_boff[64];
// tf32-rounded operands, column-pair-permuted within 8-col groups
__device__ __align__(16) float g_Af[(size_t)NPAD * WID];
__device__ __align__(16) float g_Bf[WID * WID];   // [N=256][K]

// ---------------- helpers ----------------
__device__ __forceinline__ uint32_t smem_u32(const void* p) {
    uint32_t a;
    asm("{ .reg .u64 t; cvta.to.shared.u64 t, %1; cvt.u32.u64 %0, t; }" : "=r"(a) : "l"(p));
    return a;
}
__device__ __forceinline__ void cp16(uint32_t s, const void* g) {
    asm volatile("cp.async.cg.shared.global [%0], [%1], 16;" :: "r"(s), "l"(g));
}
#define CP_COMMIT()  asm volatile("cp.async.commit_group;" ::: "memory")
#define CP_WAIT(n)   asm volatile("cp.async.wait_group %0;" :: "n"(n) : "memory")

__device__ __forceinline__ float to_tf32(float x) {
    uint32_t r;
    asm("cvt.rna.tf32.f32 %0, %1;" : "=r"(r) : "f"(x));
    return __uint_as_float(r);
}
__device__ __forceinline__ void mma_tf32(float* d, const uint32_t* a, const uint32_t* b) {
    asm volatile(
        "mma.sync.aligned.m16n8k8.row.col.f32.tf32.tf32.f32 "
        "{%0,%1,%2,%3}, {%4,%5,%6,%7}, {%8,%9}, {%0,%1,%2,%3};"
        : "+f"(d[0]), "+f"(d[1]), "+f"(d[2]), "+f"(d[3])
        : "r"(a[0]), "r"(a[1]), "r"(a[2]), "r"(a[3]), "r"(b[0]), "r"(b[1]));
}

// ---------------- dtype probe + clear deg ----------------
__global__ void k_probe_clear(const int* __restrict__ ei32) {
    int i = blockIdx.x * blockDim.x + threadIdx.x;
    if (i < NNODES) g_deg[i] = 0;
    if (i == 0) {
        int allzero = 1;
#pragma unroll
        for (int j = 0; j < 8; j++) allzero &= (ei32[2 * j + 1] == 0);
        g_i64flag = allzero;
    }
}

// ---------------- CSR build ----------------
__global__ void k_count(const void* __restrict__ ei) {
    int i = blockIdx.x * blockDim.x + threadIdx.x;
    if (i >= ETOT) return;
    int s, d;
    if (i < NEDG) {
        if (g_i64flag) {
            const long long* p = (const long long*)ei;
            s = (int)p[i]; d = (int)p[NEDG + i];
        } else {
            const int* p = (const int*)ei;
            s = p[i]; d = p[NEDG + i];
        }
    } else {
        s = i - NEDG; d = s;
    }
    g_srcE[i] = s;
    g_dst[i] = d;
    atomicAdd(&g_deg[d], 1);
}

__global__ __launch_bounds__(1024) void k_scan_blk() {
    __shared__ int wsum[32];
    int tid = threadIdx.x, lane = tid & 31, w = tid >> 5;
    int i = blockIdx.x * 1024 + tid;
    int v = (i < NNODES) ? g_deg[i] : 0;
    int x = v;
#pragma unroll
    for (int o = 1; o < 32; o <<= 1) {
        int t = __shfl_up_sync(0xffffffffu, x, o);
        if (lane >= o) x += t;
    }
    if (lane == 31) wsum[w] = x;
    __syncthreads();
    if (w == 0) {
        int s = wsum[lane];
#pragma unroll
        for (int o = 1; o < 32; o <<= 1) {
            int t = __shfl_up_sync(0xffffffffu, s, o);
            if (lane >= o) s += t;
        }
        wsum[lane] = s;
    }
    __syncthreads();
    int incl = x + (w ? wsum[w - 1] : 0);
    if (i < NNODES) g_incl[i] = incl;
    if (tid == 1023) g_bsum[blockIdx.x] = incl;
}

__global__ void k_scan_top(int nb) {
    __shared__ int ws[2];
    int tid = threadIdx.x, lane = tid & 31, wi = tid >> 5;
    int v = (tid < nb) ? g_bsum[tid] : 0;
    int x = v;
#pragma unroll
    for (int o = 1; o < 32; o <<= 1) {
        int t = __shfl_up_sync(0xffffffffu, x, o);
        if (lane >= o) x += t;
    }
    if (lane == 31) ws[wi] = x;
    __syncthreads();
    int incl = x + ((wi == 1) ? ws[0] : 0);
    if (tid < nb) g_boff[tid] = incl - v;
}

__global__ void k_scan_fix() {
    int i = blockIdx.x * blockDim.x + threadIdx.x;
    if (i >= NNODES) return;
    int incl = g_incl[i] + g_boff[i >> 10];
    g_rowptr[i + 1] = incl;
    g_cursor[i] = incl - g_deg[i];
    if (i == 0) g_rowptr[0] = 0;
}

__global__ void k_fill() {
    int i = blockIdx.x * blockDim.x + threadIdx.x;
    if (i >= ETOT) return;
    int p = atomicAdd(&g_cursor[g_dst[i]], 1);
    g_scsr[p] = g_srcE[i];
}

// ------ fp32 -> tf32 + column-pair permute (layer 0; also zeroes als/ald) ---
// within each 8-col group: out[0..7] = {c0,c4,c1,c5,c2,c6,c3,c7}
__global__ void k_splitA(const float* __restrict__ in, int n8) {
    int i = blockIdx.x * blockDim.x + threadIdx.x;
    if (i < NNODES) {
        float4 z = make_float4(0.f, 0.f, 0.f, 0.f);
        ((float4*)g_als)[i] = z;
        ((float4*)g_ald)[i] = z;
    }
    if (i >= n8) return;
    float4 u = *(const float4*)(in + (size_t)i * 8);
    float4 v = *(const float4*)(in + (size_t)i * 8 + 4);
    float4 o0 = make_float4(to_tf32(u.x), to_tf32(v.x), to_tf32(u.y), to_tf32(v.y));
    float4 o1 = make_float4(to_tf32(u.z), to_tf32(v.z), to_tf32(u.w), to_tf32(v.w));
    *(float4*)(g_Af + (size_t)i * 8)     = o0;
    *(float4*)(g_Af + (size_t)i * 8 + 4) = o1;
}

__device__ __forceinline__ int colperm(int k) {
    return (k & ~7) | (((k & 3) << 1) | ((k >> 2) & 1));
}

// W split for layers 1/2 — also clears g_als/g_ald; layer 2 also inits out
__global__ void k_splitW(const float* __restrict__ W, int K,
                         float* out, const float* __restrict__ linb) {
    int i = blockIdx.x * blockDim.x + threadIdx.x;
    if (i < NNODES) {
        float4 z = make_float4(0.f, 0.f, 0.f, 0.f);
        ((float4*)g_als)[i] = z;
        ((float4*)g_ald)[i] = z;
    }
    if (out && i < NG) out[i] = linb[0];
    if (i >= K * WID) return;
    int k = i >> 8, n = i & 255;
    g_Bf[n * K + colperm(k)] = to_tf32(W[i]);
}

__global__ void k_splitW0(const float* __restrict__ W, int K) {
    int i = blockIdx.x * blockDim.x + threadIdx.x;
    if (i >= K * WID) return;
    int k = i >> 8, n = i & 255;
    g_Bf[n * K + colperm(k)] = to_tf32(W[i]);
}

// ---------------- tf32 HMMA GEMM + fused attention epilogue ----------------
// CTA 128x128, BK=32, row stride 160B (40 floats: 32 data + 8 pad), 2-stage.
// Column-pair permuted operands -> LDS.64 fragment loads, conflict-free.
#define ROWF   160
#define OFFA3  0
#define OFFB3  20480            // 128*160
#define STG3   40960
#define GSMEM3 81920

__device__ __forceinline__ void load_stage3(uint32_t sb, int bm, int bn, int K,
                                            int k0, int tid) {
#pragma unroll
    for (int i = 0; i < 4; i++) {
        int idx = tid + i * 256;
        int row = idx >> 3, seg = idx & 7;
        uint32_t so = row * ROWF + seg * 16;
        cp16(sb + OFFA3 + so, g_Af + (size_t)(bm + row) * K + k0 + seg * 4);
        cp16(sb + OFFB3 + so, g_Bf + (size_t)(bn + row) * K + k0 + seg * 4);
    }
}

__global__ __launch_bounds__(256, 2) void k_gemm_mma(int K,
        const float* __restrict__ asrc, const float* __restrict__ adst) {
    extern __shared__ char smem[];
    uint32_t sb = smem_u32(smem);
    int tid = threadIdx.x, lane = tid & 31, w = tid >> 5;
    int bm = blockIdx.x * 128, bn = blockIdx.y * 128;
    int wm = (w >> 2) * 64, wn = (w & 3) * 32;
    int r4 = lane >> 2, c4 = lane & 3;

    float acc[4][4][4];
#pragma unroll
    for (int mt = 0; mt < 4; mt++)
#pragma unroll
        for (int nt = 0; nt < 4; nt++)
#pragma unroll
            for (int j = 0; j < 4; j++) acc[mt][nt][j] = 0.f;

    uint32_t a_off = (uint32_t)(wm + r4) * ROWF;
    uint32_t b_off = (uint32_t)(wn + r4) * ROWF;

    const int nc = K >> 5;
    load_stage3(sb, bm, bn, K, 0, tid);
    CP_COMMIT();

    for (int kc = 0; kc < nc; kc++) {
        if (kc + 1 < nc) {
            load_stage3(sb + ((kc + 1) & 1) * STG3, bm, bn, K, (kc + 1) << 5, tid);
            CP_COMMIT();
            CP_WAIT(1);
        } else {
            CP_WAIT(0);
        }
        __syncthreads();
        const char* st = smem + (kc & 1) * STG3;
#pragma unroll
        for (int s = 0; s < 4; s++) {
            int kb = s * 32 + c4 * 8;          // byte offset: cols (c4, c4+4) pair
            uint32_t a[4][4], b[4][2];
#pragma unroll
            for (int mt = 0; mt < 4; mt++) {
                const char* p = st + OFFA3 + a_off + mt * (16 * ROWF) + kb;
                uint2 lo = *(const uint2*)(p);
                uint2 hi = *(const uint2*)(p + 8 * ROWF);
                a[mt][0] = lo.x; a[mt][1] = hi.x;
                a[mt][2] = lo.y; a[mt][3] = hi.y;
            }
#pragma unroll
            for (int nt = 0; nt < 4; nt++) {
                const char* p = st + OFFB3 + b_off + nt * (8 * ROWF) + kb;
                uint2 bb = *(const uint2*)(p);
                b[nt][0] = bb.x; b[nt][1] = bb.y;
            }
#pragma unroll
            for (int nt = 0; nt < 4; nt++)
#pragma unroll
                for (int mt = 0; mt < 4; mt++)
                    mma_tf32(acc[mt][nt], a[mt], b[nt]);
        }
        __syncthreads();
    }

    // ---- fused epilogue: store g_h tile + per-row attention partial dots ---
    int r = lane >> 2, cq = lane & 3;
    int hh = ((bn + wn) >> 6) & 3;
    float2 as2[4], ad2[4];
#pragma unroll
    for (int nt = 0; nt < 4; nt++) {
        int col = bn + wn + nt * 8 + cq * 2;
        as2[nt] = *(const float2*)(asrc + col);
        ad2[nt] = *(const float2*)(adst + col);
    }
#pragma unroll
    for (int mt = 0; mt < 4; mt++) {
        int row0 = bm + wm + mt * 16 + r;
        float ps0 = 0.f, pd0 = 0.f, ps1 = 0.f, pd1 = 0.f;
#pragma unroll
        for (int nt = 0; nt < 4; nt++) {
            int col = bn + wn + nt * 8 + cq * 2;
            ps0 += acc[mt][nt][0] * as2[nt].x + acc[mt][nt][1] * as2[nt].y;
            pd0 += acc[mt][nt][0] * ad2[nt].x + acc[mt][nt][1] * ad2[nt].y;
            ps1 += acc[mt][nt][2] * as2[nt].x + acc[mt][nt][3] * as2[nt].y;
            pd1 += acc[mt][nt][2] * ad2[nt].x + acc[mt][nt][3] * ad2[nt].y;
            if (row0 < NNODES)
                *(float2*)(g_h + (size_t)row0 * WID + col) =
                    make_float2(acc[mt][nt][0], acc[mt][nt][1]);
            if (row0 + 8 < NNODES)
                *(float2*)(g_h + (size_t)(row0 + 8) * WID + col) =
                    make_float2(acc[mt][nt][2], acc[mt][nt][3]);
        }
        ps0 += __shfl_down_sync(0xffffffffu, ps0, 2);
        ps0 += __shfl_down_sync(0xffffffffu, ps0, 1);
        pd0 += __shfl_down_sync(0xffffffffu, pd0, 2);
        pd0 += __shfl_down_sync(0xffffffffu, pd0, 1);
        ps1 += __shfl_down_sync(0xffffffffu, ps1, 2);
        ps1 += __shfl_down_sync(0xffffffffu, ps1, 1);
        pd1 += __shfl_down_sync(0xffffffffu, pd1, 2);
        pd1 += __shfl_down_sync(0xffffffffu, pd1, 1);
        if (cq == 0) {
            if (row0 < NNODES) {
                atomicAdd(&g_als[row0 * 4 + hh], ps0);
                atomicAdd(&g_ald[row0 * 4 + hh], pd0);
            }
            if (row0 + 8 < NNODES) {
                atomicAdd(&g_als[(row0 + 8) * 4 + hh], ps1);
                atomicAdd(&g_ald[(row0 + 8) * 4 + hh], pd1);
            }
        }
    }
}

// --------- aggregation: WARP per node — no block syncs ---------
__global__ __launch_bounds__(128) void k_aggregate(const float* __restrict__ bias, int dosplit,
        const float* __restrict__ linw, const void* __restrict__ batch, float* out) {
    __shared__ float s_al[4][4][DCAPW];   // [warp][head][edge]
    __shared__ int   s_src[4][DCAPW];
    int wid = threadIdx.x >> 5, lane = threadIdx.x & 31;
    int n = blockIdx.x * 4 + wid;
    int start = g_rowptr[n];
    int deg = g_rowptr[n + 1] - start;
    int g = lane >> 3;
    int j = lane & 7;

    float4 aldn = ((const float4*)g_ald)[n];
    float inv;
    float acc[8];
#pragma unroll
    for (int k = 0; k < 8; k++) acc[k] = 0.f;
    int c = lane * 8;

    if (deg <= DCAPW) {
        for (int i = lane; i < deg; i += 32) {
            int s = g_scsr[start + i];
            s_src[wid][i] = s;
            float4 a = ((const float4*)g_als)[s];
            float t0 = a.x + aldn.x; t0 = t0 > 0.f ? t0 : 0.2f * t0;
            float t1 = a.y + aldn.y; t1 = t1 > 0.f ? t1 : 0.2f * t1;
            float t2 = a.z + aldn.z; t2 = t2 > 0.f ? t2 : 0.2f * t2;
            float t3 = a.w + aldn.w; t3 = t3 > 0.f ? t3 : 0.2f * t3;
            s_al[wid][0][i] = t0; s_al[wid][1][i] = t1;
            s_al[wid][2][i] = t2; s_al[wid][3][i] = t3;
        }
        __syncwarp();

        float mx = -1e30f;
        for (int i = j; i < deg; i += 8) mx = fmaxf(mx, s_al[wid][g][i]);
#pragma unroll
        for (int o = 4; o; o >>= 1) mx = fmaxf(mx, __shfl_xor_sync(0xffffffffu, mx, o));
        float sum = 0.f;
        for (int i = j; i < deg; i += 8) {
            float ex = expf(s_al[wid][g][i] - mx);
            s_al[wid][g][i] = ex;
            sum += ex;
        }
#pragma unroll
        for (int o = 4; o; o >>= 1) sum += __shfl_xor_sync(0xffffffffu, sum, o);
        inv = 1.f / (sum + 1e-16f);
        __syncwarp();

        const float* alp = s_al[wid][g];
        const int*   sp  = s_src[wid];
        float b[8];
#pragma unroll
        for (int k = 0; k < 8; k++) b[k] = 0.f;
        int i = 0;
        for (; i + 2 <= deg; i += 2) {
            float p = alp[i], q = alp[i + 1];
            const float* r0 = g_h + (size_t)sp[i] * WID + c;
            const float* r1 = g_h + (size_t)sp[i + 1] * WID + c;
            float4 u0 = *(const float4*)r0, u1 = *(const float4*)(r0 + 4);
            float4 w0 = *(const float4*)r1, w1 = *(const float4*)(r1 + 4);
            acc[0] += p * u0.x; acc[1] += p * u0.y; acc[2] += p * u0.z; acc[3] += p * u0.w;
            acc[4] += p * u1.x; acc[5] += p * u1.y; acc[6] += p * u1.z; acc[7] += p * u1.w;
            b[0] += q * w0.x; b[1] += q * w0.y; b[2] += q * w0.z; b[3] += q * w0.w;
            b[4] += q * w1.x; b[5] += q * w1.y; b[6] += q * w1.z; b[7] += q * w1.w;
        }
        if (i < deg) {
            float p = alp[i];
            const float* r0 = g_h + (size_t)sp[i] * WID + c;
            float4 u0 = *(const float4*)r0, u1 = *(const float4*)(r0 + 4);
            acc[0] += p * u0.x; acc[1] += p * u0.y; acc[2] += p * u0.z; acc[3] += p * u0.w;
            acc[4] += p * u1.x; acc[5] += p * u1.y; acc[6] += p * u1.z; acc[7] += p * u1.w;
        }
#pragma unroll
        for (int k = 0; k < 8; k++) acc[k] += b[k];
    } else {
        // -------- fallback: deg > DCAPW, warp-local via g_esc ----------
        float4 mx4 = make_float4(-1e30f, -1e30f, -1e30f, -1e30f);
        for (int i = lane; i < deg; i += 32) {
            float4 a = ((const float4*)g_als)[g_scsr[start + i]];
            a.x += aldn.x; a.x = a.x > 0.f ? a.x : 0.2f * a.x;
            a.y += aldn.y; a.y = a.y > 0.f ? a.y : 0.2f * a.y;
            a.z += aldn.z; a.z = a.z > 0.f ? a.z : 0.2f * a.z;
            a.w += aldn.w; a.w = a.w > 0.f ? a.w : 0.2f * a.w;
            ((float4*)g_esc)[start + i] = a;
            mx4.x = fmaxf(mx4.x, a.x); mx4.y = fmaxf(mx4.y, a.y);
            mx4.z = fmaxf(mx4.z, a.z); mx4.w = fmaxf(mx4.w, a.w);
        }
#pragma unroll
        for (int o = 16; o; o >>= 1) {
            mx4.x = fmaxf(mx4.x, __shfl_xor_sync(0xffffffffu, mx4.x, o));
            mx4.y = fmaxf(mx4.y, __shfl_xor_sync(0xffffffffu, mx4.y, o));
            mx4.z = fmaxf(mx4.z, __shfl_xor_sync(0xffffffffu, mx4.z, o));
            mx4.w = fmaxf(mx4.w, __shfl_xor_sync(0xffffffffu, mx4.w, o));
        }
        __threadfence_block();
        __syncwarp();
        float4 sum4 = make_float4(0.f, 0.f, 0.f, 0.f);
        for (int i = lane; i < deg; i += 32) {
            float4 e = ((float4*)g_esc)[start + i];
            e.x = expf(e.x - mx4.x); e.y = expf(e.y - mx4.y);
            e.z = expf(e.z - mx4.z); e.w = expf(e.w - mx4.w);
            ((float4*)g_esc)[start + i] = e;
            sum4.x += e.x; sum4.y += e.y; sum4.z += e.z; sum4.w += e.w;
        }
#pragma unroll
        for (int o = 16; o; o >>= 1) {
            sum4.x += __shfl_xor_sync(0xffffffffu, sum4.x, o);
            sum4.y += __shfl_xor_sync(0xffffffffu, sum4.y, o);
            sum4.z += __shfl_xor_sync(0xffffffffu, sum4.z, o);
            sum4.w += __shfl_xor_sync(0xffffffffu, sum4.w, o);
        }
        float sums[4] = {sum4.x, sum4.y, sum4.z, sum4.w};
        inv = 1.f / (sums[g] + 1e-16f);
        __threadfence_block();
        __syncwarp();
        for (int i = 0; i < deg; i++) {
            float a = g_esc[(size_t)(start + i) * 4 + g];
            const float* r0 = g_h + (size_t)g_scsr[start + i] * WID + c;
            float4 u0 = *(const float4*)r0, u1 = *(const float4*)(r0 + 4);
            acc[0] += a * u0.x; acc[1] += a * u0.y; acc[2] += a * u0.z; acc[3] += a * u0.w;
            acc[4] += a * u1.x; acc[5] += a * u1.y; acc[6] += a * u1.z; acc[7] += a * u1.w;
        }
    }

    // ---- epilogue: bias + ELU, then split (tf32, col-pair permuted) / pool --
    float4 b0 = *(const float4*)(bias + c), b1 = *(const float4*)(bias + c + 4);
    float v[8];
    v[0] = acc[0] * inv + b0.x; v[1] = acc[1] * inv + b0.y;
    v[2] = acc[2] * inv + b0.z; v[3] = acc[3] * inv + b0.w;
    v[4] = acc[4] * inv + b1.x; v[5] = acc[5] * inv + b1.y;
    v[6] = acc[6] * inv + b1.z; v[7] = acc[7] * inv + b1.w;
#pragma unroll
    for (int k = 0; k < 8; k++) v[k] = v[k] > 0.f ? v[k] : expm1f(v[k]);

    if (dosplit) {
        // permuted order: {v0,v4,v1,v5}, {v2,v6,v3,v7}
        float4 o0 = make_float4(to_tf32(v[0]), to_tf32(v[4]), to_tf32(v[1]), to_tf32(v[5]));
        float4 o1 = make_float4(to_tf32(v[2]), to_tf32(v[6]), to_tf32(v[3]), to_tf32(v[7]));
        *(float4*)(g_Af + (size_t)n * WID + c)     = o0;
        *(float4*)(g_Af + (size_t)n * WID + c + 4) = o1;
    } else {
        float4 w0 = *(const float4*)(linw + c), w1 = *(const float4*)(linw + c + 4);
        float part = v[0] * w0.x + v[1] * w0.y + v[2] * w0.z + v[3] * w0.w
                   + v[4] * w1.x + v[5] * w1.y + v[6] * w1.z + v[7] * w1.w;
#pragma unroll
        for (int o = 16; o; o >>= 1) part += __shfl_xor_sync(0xffffffffu, part, o);
        if (lane == 0) {
            int gg = g_i64flag ? (int)((const long long*)batch)[n]
                               : ((const int*)batch)[n];
            atomicAdd(&out[gg], part);
        }
    }
}

// ---------------- launch ----------------
extern "C" void kernel_launch(void* const* d_in, const int* in_sizes, int n_in,
                              void* d_out, int out_size) {
    const float* x     = (const float*)d_in[0];
    const void*  ei    = d_in[1];
    const void*  batch = d_in[3];
    const float* W[3]    = {(const float*)d_in[4],  (const float*)d_in[8],  (const float*)d_in[12]};
    const float* asrc[3] = {(const float*)d_in[5],  (const float*)d_in[9],  (const float*)d_in[13]};
    const float* adst[3] = {(const float*)d_in[6],  (const float*)d_in[10], (const float*)d_in[14]};
    const float* bb[3]   = {(const float*)d_in[7],  (const float*)d_in[11], (const float*)d_in[15]};
    const float* linw = (const float*)d_in[16];
    const float* linb = (const float*)d_in[17];
    float* out = (float*)d_out;

    static int smem_set = 0;
    if (!smem_set) {
        cudaFuncSetAttribute(k_gemm_mma, cudaFuncAttributeMaxDynamicSharedMemorySize, GSMEM3);
        smem_set = 1;
    }

    dim3 ggrid(MTILES, 2);
    int nodeGrid = (NNODES + 255) / 256;
    int aggGrid = NNODES / 4;   // 12500

    // probe + clear, layer-0 tf32 round+permute (also zeroes als/ald), W0, GEMM0
    k_probe_clear<<<nodeGrid, 256>>>((const int*)ei);
    k_splitA<<<(NNODES * 128 / 8 + 255) / 256, 256>>>(x, NNODES * 128 / 8);
    k_splitW0<<<(128 * WID + 255) / 256, 256>>>(W[0], 128);
    k_gemm_mma<<<ggrid, 256, GSMEM3>>>(128, asrc[0], adst[0]);

    // CSR build (before first aggregate)
    k_count<<<(ETOT + 255) / 256, 256>>>(ei);
    int nb = (NNODES + 1023) / 1024;
    k_scan_blk<<<nb, 1024>>>();
    k_scan_top<<<1, 64>>>(nb);
    k_scan_fix<<<nodeGrid, 256>>>();
    k_fill<<<(ETOT + 255) / 256, 256>>>();

    // layer 0 tail
    k_aggregate<<<aggGrid, 128>>>(bb[0], 1, nullptr, nullptr, nullptr);

    // layer 1 (K=256); splitW also clears g_als/ald
    k_splitW<<<(256 * WID + 255) / 256, 256>>>(W[1], 256, nullptr, nullptr);
    k_gemm_mma<<<ggrid, 256, GSMEM3>>>(256, asrc[1], adst[1]);
    k_aggregate<<<aggGrid, 128>>>(bb[1], 1, nullptr, nullptr, nullptr);

    // layer 2 (K=256): splitW also inits out; aggregate fuses pooling + head
    k_splitW<<<(256 * WID + 255) / 256, 256>>>(W[2], 256, out, linb);
    k_gemm_mma<<<ggrid, 256, GSMEM3>>>(256, asrc[2], adst[2]);
    k_aggregate<<<aggGrid, 128>>>(bb[2], 0, linw, batch, out);
}

// round 15
// speedup vs baseline: 1.0761x; 1.0761x over previous
#include <cuda_runtime.h>
#include <math.h>
#include <stdint.h>

#define NNODES 50000
#define NEDG   400000
#define ETOT   450000
#define WID    256
#define NG     256
#define NPAD   50048        // 391 * 128
#define MTILES 391
#define DCAPW  64           // per-node bucket capacity (fast path)

// ---------------- scratch globals ----------------
__device__ float g_h[(size_t)NNODES * WID];
__device__ float g_als[NNODES * 4];
__device__ float g_ald[NNODES * 4];
__device__ int   g_bkt[(size_t)NNODES * DCAPW];   // bucket CSR: src per slot
__device__ int   g_ovfs[ETOT];                    // overflow src (never used in practice)
__device__ int   g_ovfd[ETOT];                    // overflow dst
__device__ int   g_ovf_cnt;
__device__ int   g_deg[NNODES];
__device__ int   g_i64flag;
// tf32-rounded operands (zero-init covers M padding)
__device__ __align__(16) float g_Af[(size_t)NPAD * WID];
__device__ __align__(16) float g_Bf[WID * WID];   // [N=256][K]

// ---------------- helpers ----------------
__device__ __forceinline__ uint32_t smem_u32(const void* p) {
    uint32_t a;
    asm("{ .reg .u64 t; cvta.to.shared.u64 t, %1; cvt.u32.u64 %0, t; }" : "=r"(a) : "l"(p));
    return a;
}
__device__ __forceinline__ void cp16(uint32_t s, const void* g) {
    asm volatile("cp.async.cg.shared.global [%0], [%1], 16;" :: "r"(s), "l"(g));
}
#define CP_COMMIT()  asm volatile("cp.async.commit_group;" ::: "memory")
#define CP_WAIT(n)   asm volatile("cp.async.wait_group %0;" :: "n"(n) : "memory")

__device__ __forceinline__ float to_tf32(float x) {
    uint32_t r;
    asm("cvt.rna.tf32.f32 %0, %1;" : "=r"(r) : "f"(x));
    return __uint_as_float(r);
}
__device__ __forceinline__ void mma_tf32(float* d, const uint32_t* a, const uint32_t* b) {
    asm volatile(
        "mma.sync.aligned.m16n8k8.row.col.f32.tf32.tf32.f32 "
        "{%0,%1,%2,%3}, {%4,%5,%6,%7}, {%8,%9}, {%0,%1,%2,%3};"
        : "+f"(d[0]), "+f"(d[1]), "+f"(d[2]), "+f"(d[3])
        : "r"(a[0]), "r"(a[1]), "r"(a[2]), "r"(a[3]), "r"(b[0]), "r"(b[1]));
}
__device__ __forceinline__ float leaky(float v) { return v > 0.f ? v : 0.2f * v; }

// ---------------- dtype probe + clear deg ----------------
__global__ void k_probe_clear(const int* __restrict__ ei32) {
    int i = blockIdx.x * blockDim.x + threadIdx.x;
    if (i < NNODES) g_deg[i] = 0;
    if (i == 0) {
        g_ovf_cnt = 0;
        int allzero = 1;
#pragma unroll
        for (int j = 0; j < 8; j++) allzero &= (ei32[2 * j + 1] == 0);
        g_i64flag = allzero;
    }
}

// ---------------- bucket CSR build (no scan) ----------------
__global__ void k_count(const void* __restrict__ ei) {
    int i = blockIdx.x * blockDim.x + threadIdx.x;
    if (i >= ETOT) return;
    int s, d;
    if (i < NEDG) {
        if (g_i64flag) {
            const long long* p = (const long long*)ei;
            s = (int)p[i]; d = (int)p[NEDG + i];
        } else {
            const int* p = (const int*)ei;
            s = p[i]; d = p[NEDG + i];
        }
    } else {
        s = i - NEDG; d = s;
    }
    int slot = atomicAdd(&g_deg[d], 1);
    if (slot < DCAPW) {
        g_bkt[(size_t)d * DCAPW + slot] = s;
    } else {
        int o = atomicAdd(&g_ovf_cnt, 1);
        g_ovfs[o] = s;
        g_ovfd[o] = d;
    }
}

// ---------------- fp32 -> tf32 round (layer 0; also zeroes g_als/ald) -------
__global__ void k_splitA(const float* __restrict__ in, int n4) {
    int i = blockIdx.x * blockDim.x + threadIdx.x;
    if (i < NNODES) {
        float4 z = make_float4(0.f, 0.f, 0.f, 0.f);
        ((float4*)g_als)[i] = z;
        ((float4*)g_ald)[i] = z;
    }
    if (i >= n4) return;
    float4 v = *(const float4*)(in + (size_t)i * 4);
    v.x = to_tf32(v.x); v.y = to_tf32(v.y);
    v.z = to_tf32(v.z); v.w = to_tf32(v.w);
    ((float4*)g_Af)[i] = v;
}

// W split for layers 1/2 — also clears g_als/g_ald; layer 2 also inits out
__global__ void k_splitW(const float* __restrict__ W, int K,
                         float* out, const float* __restrict__ linb) {
    int i = blockIdx.x * blockDim.x + threadIdx.x;
    if (i < NNODES) {
        float4 z = make_float4(0.f, 0.f, 0.f, 0.f);
        ((float4*)g_als)[i] = z;
        ((float4*)g_ald)[i] = z;
    }
    if (out && i < NG) out[i] = linb[0];
    if (i >= K * WID) return;
    int k = i >> 8, n = i & 255;
    g_Bf[n * K + k] = to_tf32(W[i]);
}

// W split for layer 0 (no clear — splitA does it)
__global__ void k_splitW0(const float* __restrict__ W, int K) {
    int i = blockIdx.x * blockDim.x + threadIdx.x;
    if (i >= K * WID) return;
    int k = i >> 8, n = i & 255;
    g_Bf[n * K + k] = to_tf32(W[i]);
}

// ---------------- tf32 HMMA GEMM + fused attention epilogue ----------------
// CTA 128x128, BK=32, row stride 144B (36 floats), 2-stage cp.async, 2 CTA/SM.
#define ROWF   144
#define OFFA3  0
#define OFFB3  18432            // 128*144
#define STG3   36864
#define GSMEM3 73728

__device__ __forceinline__ void load_stage3(uint32_t sb, int bm, int bn, int K,
                                            int k0, int tid) {
#pragma unroll
    for (int i = 0; i < 4; i++) {
        int idx = tid + i * 256;
        int row = idx >> 3, seg = idx & 7;
        uint32_t so = row * ROWF + seg * 16;
        cp16(sb + OFFA3 + so, g_Af + (size_t)(bm + row) * K + k0 + seg * 4);
        cp16(sb + OFFB3 + so, g_Bf + (size_t)(bn + row) * K + k0 + seg * 4);
    }
}

__global__ __launch_bounds__(256, 2) void k_gemm_mma(int K,
        const float* __restrict__ asrc, const float* __restrict__ adst) {
    extern __shared__ char smem[];
    uint32_t sb = smem_u32(smem);
    int tid = threadIdx.x, lane = tid & 31, w = tid >> 5;
    int bm = blockIdx.x * 128, bn = blockIdx.y * 128;
    int wm = (w >> 2) * 64, wn = (w & 3) * 32;
    int r4 = lane >> 2, c4 = lane & 3;

    float acc[4][4][4];
#pragma unroll
    for (int mt = 0; mt < 4; mt++)
#pragma unroll
        for (int nt = 0; nt < 4; nt++)
#pragma unroll
            for (int j = 0; j < 4; j++) acc[mt][nt][j] = 0.f;

    uint32_t a_off = (uint32_t)(wm + r4) * ROWF + c4 * 4;
    uint32_t b_off = (uint32_t)(wn + r4) * ROWF + c4 * 4;

    const int nc = K >> 5;
    load_stage3(sb, bm, bn, K, 0, tid);
    CP_COMMIT();

    for (int kc = 0; kc < nc; kc++) {
        if (kc + 1 < nc) {
            load_stage3(sb + ((kc + 1) & 1) * STG3, bm, bn, K, (kc + 1) << 5, tid);
            CP_COMMIT();
            CP_WAIT(1);
        } else {
            CP_WAIT(0);
        }
        __syncthreads();
        const char* st = smem + (kc & 1) * STG3;
#pragma unroll
        for (int s = 0; s < 4; s++) {
            int kb = s * 32;                       // 8 floats per k8 step
            uint32_t a[4][4], b[4][2];
#pragma unroll
            for (int mt = 0; mt < 4; mt++) {
                const char* p = st + OFFA3 + a_off + mt * (16 * ROWF) + kb;
                a[mt][0] = *(const uint32_t*)(p);
                a[mt][1] = *(const uint32_t*)(p + 8 * ROWF);
                a[mt][2] = *(const uint32_t*)(p + 16);
                a[mt][3] = *(const uint32_t*)(p + 8 * ROWF + 16);
            }
#pragma unroll
            for (int nt = 0; nt < 4; nt++) {
                const char* p = st + OFFB3 + b_off + nt * (8 * ROWF) + kb;
                b[nt][0] = *(const uint32_t*)(p);
                b[nt][1] = *(const uint32_t*)(p + 16);
            }
#pragma unroll
            for (int nt = 0; nt < 4; nt++)
#pragma unroll
                for (int mt = 0; mt < 4; mt++)
                    mma_tf32(acc[mt][nt], a[mt], b[nt]);
        }
        __syncthreads();
    }

    // ---- fused epilogue: store g_h tile + per-row attention partial dots ---
    int r = lane >> 2, cq = lane & 3;
    int hh = ((bn + wn) >> 6) & 3;
    float2 as2[4], ad2[4];
#pragma unroll
    for (int nt = 0; nt < 4; nt++) {
        int col = bn + wn + nt * 8 + cq * 2;
        as2[nt] = *(const float2*)(asrc + col);
        ad2[nt] = *(const float2*)(adst + col);
    }
#pragma unroll
    for (int mt = 0; mt < 4; mt++) {
        int row0 = bm + wm + mt * 16 + r;
        float ps0 = 0.f, pd0 = 0.f, ps1 = 0.f, pd1 = 0.f;
#pragma unroll
        for (int nt = 0; nt < 4; nt++) {
            int col = bn + wn + nt * 8 + cq * 2;
            ps0 += acc[mt][nt][0] * as2[nt].x + acc[mt][nt][1] * as2[nt].y;
            pd0 += acc[mt][nt][0] * ad2[nt].x + acc[mt][nt][1] * ad2[nt].y;
            ps1 += acc[mt][nt][2] * as2[nt].x + acc[mt][nt][3] * as2[nt].y;
            pd1 += acc[mt][nt][2] * ad2[nt].x + acc[mt][nt][3] * ad2[nt].y;
            if (row0 < NNODES)
                *(float2*)(g_h + (size_t)row0 * WID + col) =
                    make_float2(acc[mt][nt][0], acc[mt][nt][1]);
            if (row0 + 8 < NNODES)
                *(float2*)(g_h + (size_t)(row0 + 8) * WID + col) =
                    make_float2(acc[mt][nt][2], acc[mt][nt][3]);
        }
        ps0 += __shfl_down_sync(0xffffffffu, ps0, 2);
        ps0 += __shfl_down_sync(0xffffffffu, ps0, 1);
        pd0 += __shfl_down_sync(0xffffffffu, pd0, 2);
        pd0 += __shfl_down_sync(0xffffffffu, pd0, 1);
        ps1 += __shfl_down_sync(0xffffffffu, ps1, 2);
        ps1 += __shfl_down_sync(0xffffffffu, ps1, 1);
        pd1 += __shfl_down_sync(0xffffffffu, pd1, 2);
        pd1 += __shfl_down_sync(0xffffffffu, pd1, 1);
        if (cq == 0) {
            if (row0 < NNODES) {
                atomicAdd(&g_als[row0 * 4 + hh], ps0);
                atomicAdd(&g_ald[row0 * 4 + hh], pd0);
            }
            if (row0 + 8 < NNODES) {
                atomicAdd(&g_als[(row0 + 8) * 4 + hh], ps1);
                atomicAdd(&g_ald[(row0 + 8) * 4 + hh], pd1);
            }
        }
    }
}

// --------- aggregation: WARP per node, bucket CSR — no block syncs ---------
// lane owns channels lane*8..lane*8+7; head = lane>>3 (8-lane groups).
__global__ __launch_bounds__(128) void k_aggregate(const float* __restrict__ bias, int dosplit,
        const float* __restrict__ linw, const void* __restrict__ batch, float* out) {
    __shared__ float s_al[4][4][DCAPW];   // [warp][head][edge]
    __shared__ int   s_src[4][DCAPW];
    int wid = threadIdx.x >> 5, lane = threadIdx.x & 31;
    int n = blockIdx.x * 4 + wid;
    const int* bkt = g_bkt + (size_t)n * DCAPW;
    int deg = g_deg[n];
    int g = lane >> 3;
    int j = lane & 7;

    float4 aldn = ((const float4*)g_ald)[n];
    float inv;
    float acc[8];
#pragma unroll
    for (int k = 0; k < 8; k++) acc[k] = 0.f;
    int c = lane * 8;

    if (deg <= DCAPW) {
        for (int i = lane; i < deg; i += 32) {
            int s = bkt[i];
            s_src[wid][i] = s;
            float4 a = ((const float4*)g_als)[s];
            s_al[wid][0][i] = leaky(a.x + aldn.x);
            s_al[wid][1][i] = leaky(a.y + aldn.y);
            s_al[wid][2][i] = leaky(a.z + aldn.z);
            s_al[wid][3][i] = leaky(a.w + aldn.w);
        }
        __syncwarp();

        float mx = -1e30f;
        for (int i = j; i < deg; i += 8) mx = fmaxf(mx, s_al[wid][g][i]);
#pragma unroll
        for (int o = 4; o; o >>= 1) mx = fmaxf(mx, __shfl_xor_sync(0xffffffffu, mx, o));
        float sum = 0.f;
        for (int i = j; i < deg; i += 8) {
            float ex = expf(s_al[wid][g][i] - mx);
            s_al[wid][g][i] = ex;
            sum += ex;
        }
#pragma unroll
        for (int o = 4; o; o >>= 1) sum += __shfl_xor_sync(0xffffffffu, sum, o);
        inv = 1.f / (sum + 1e-16f);
        __syncwarp();

        const float* alp = s_al[wid][g];
        const int*   sp  = s_src[wid];
        float b[8];
#pragma unroll
        for (int k = 0; k < 8; k++) b[k] = 0.f;
        int i = 0;
        for (; i + 2 <= deg; i += 2) {
            float p = alp[i], q = alp[i + 1];
            const float* r0 = g_h + (size_t)sp[i] * WID + c;
            const float* r1 = g_h + (size_t)sp[i + 1] * WID + c;
            float4 u0 = *(const float4*)r0, u1 = *(const float4*)(r0 + 4);
            float4 w0 = *(const float4*)r1, w1 = *(const float4*)(r1 + 4);
            acc[0] += p * u0.x; acc[1] += p * u0.y; acc[2] += p * u0.z; acc[3] += p * u0.w;
            acc[4] += p * u1.x; acc[5] += p * u1.y; acc[6] += p * u1.z; acc[7] += p * u1.w;
            b[0] += q * w0.x; b[1] += q * w0.y; b[2] += q * w0.z; b[3] += q * w0.w;
            b[4] += q * w1.x; b[5] += q * w1.y; b[6] += q * w1.z; b[7] += q * w1.w;
        }
        if (i < deg) {
            float p = alp[i];
            const float* r0 = g_h + (size_t)sp[i] * WID + c;
            float4 u0 = *(const float4*)r0, u1 = *(const float4*)(r0 + 4);
            acc[0] += p * u0.x; acc[1] += p * u0.y; acc[2] += p * u0.z; acc[3] += p * u0.w;
            acc[4] += p * u1.x; acc[5] += p * u1.y; acc[6] += p * u1.z; acc[7] += p * u1.w;
        }
#pragma unroll
        for (int k = 0; k < 8; k++) acc[k] += b[k];
    } else {
        // -------- fallback: deg > DCAPW (bucket + overflow list; ~never) -----
        int nov = g_ovf_cnt;
        float aldv[4] = {aldn.x, aldn.y, aldn.z, aldn.w};
        // pass 1: per-head max over bucket + matching overflow edges
        float4 mx4 = make_float4(-1e30f, -1e30f, -1e30f, -1e30f);
        for (int i = lane; i < DCAPW; i += 32) {
            float4 a = ((const float4*)g_als)[bkt[i]];
            mx4.x = fmaxf(mx4.x, leaky(a.x + aldn.x));
            mx4.y = fmaxf(mx4.y, leaky(a.y + aldn.y));
            mx4.z = fmaxf(mx4.z, leaky(a.z + aldn.z));
            mx4.w = fmaxf(mx4.w, leaky(a.w + aldn.w));
        }
        for (int i = lane; i < nov; i += 32) {
            if (g_ovfd[i] != n) continue;
            float4 a = ((const float4*)g_als)[g_ovfs[i]];
            mx4.x = fmaxf(mx4.x, leaky(a.x + aldn.x));
            mx4.y = fmaxf(mx4.y, leaky(a.y + aldn.y));
            mx4.z = fmaxf(mx4.z, leaky(a.z + aldn.z));
            mx4.w = fmaxf(mx4.w, leaky(a.w + aldn.w));
        }
#pragma unroll
        for (int o = 16; o; o >>= 1) {
            mx4.x = fmaxf(mx4.x, __shfl_xor_sync(0xffffffffu, mx4.x, o));
            mx4.y = fmaxf(mx4.y, __shfl_xor_sync(0xffffffffu, mx4.y, o));
            mx4.z = fmaxf(mx4.z, __shfl_xor_sync(0xffffffffu, mx4.z, o));
            mx4.w = fmaxf(mx4.w, __shfl_xor_sync(0xffffffffu, mx4.w, o));
        }
        float mxv[4] = {mx4.x, mx4.y, mx4.z, mx4.w};
        // pass 2: per-head sum
        float4 sum4 = make_float4(0.f, 0.f, 0.f, 0.f);
        for (int i = lane; i < DCAPW; i += 32) {
            float4 a = ((const float4*)g_als)[bkt[i]];
            sum4.x += expf(leaky(a.x + aldn.x) - mx4.x);
            sum4.y += expf(leaky(a.y + aldn.y) - mx4.y);
            sum4.z += expf(leaky(a.z + aldn.z) - mx4.z);
            sum4.w += expf(leaky(a.w + aldn.w) - mx4.w);
        }
        for (int i = lane; i < nov; i += 32) {
            if (g_ovfd[i] != n) continue;
            float4 a = ((const float4*)g_als)[g_ovfs[i]];
            sum4.x += expf(leaky(a.x + aldn.x) - mx4.x);
            sum4.y += expf(leaky(a.y + aldn.y) - mx4.y);
            sum4.z += expf(leaky(a.z + aldn.z) - mx4.z);
            sum4.w += expf(leaky(a.w + aldn.w) - mx4.w);
        }
#pragma unroll
        for (int o = 16; o; o >>= 1) {
            sum4.x += __shfl_xor_sync(0xffffffffu, sum4.x, o);
            sum4.y += __shfl_xor_sync(0xffffffffu, sum4.y, o);
            sum4.z += __shfl_xor_sync(0xffffffffu, sum4.z, o);
            sum4.w += __shfl_xor_sync(0xffffffffu, sum4.w, o);
        }
        float sums[4] = {sum4.x, sum4.y, sum4.z, sum4.w};
        inv = 1.f / (sums[g] + 1e-16f);
        // pass 3: aggregate (serial over edges; each lane its 8 channels)
        float mxg = mxv[g], aldg = aldv[g];
        for (int i = 0; i < DCAPW; i++) {
            int s = bkt[i];
            float alpha = expf(leaky(g_als[s * 4 + g] + aldg) - mxg);
            const float* r0 = g_h + (size_t)s * WID + c;
            float4 u0 = *(const float4*)r0, u1 = *(const float4*)(r0 + 4);
            acc[0] += alpha * u0.x; acc[1] += alpha * u0.y;
            acc[2] += alpha * u0.z; acc[3] += alpha * u0.w;
            acc[4] += alpha * u1.x; acc[5] += alpha * u1.y;
            acc[6] += alpha * u1.z; acc[7] += alpha * u1.w;
        }
        for (int i = 0; i < nov; i++) {
            if (g_ovfd[i] != n) continue;
            int s = g_ovfs[i];
            float alpha = expf(leaky(g_als[s * 4 + g] + aldg) - mxg);
            const float* r0 = g_h + (size_t)s * WID + c;
            float4 u0 = *(const float4*)r0, u1 = *(const float4*)(r0 + 4);
            acc[0] += alpha * u0.x; acc[1] += alpha * u0.y;
            acc[2] += alpha * u0.z; acc[3] += alpha * u0.w;
            acc[4] += alpha * u1.x; acc[5] += alpha * u1.y;
            acc[6] += alpha * u1.z; acc[7] += alpha * u1.w;
        }
    }

    // ---- epilogue: bias + ELU, then split (tf32) or pool ----
    float4 b0 = *(const float4*)(bias + c), b1 = *(const float4*)(bias + c + 4);
    float v[8];
    v[0] = acc[0] * inv + b0.x; v[1] = acc[1] * inv + b0.y;
    v[2] = acc[2] * inv + b0.z; v[3] = acc[3] * inv + b0.w;
    v[4] = acc[4] * inv + b1.x; v[5] = acc[5] * inv + b1.y;
    v[6] = acc[6] * inv + b1.z; v[7] = acc[7] * inv + b1.w;
#pragma unroll
    for (int k = 0; k < 8; k++) v[k] = v[k] > 0.f ? v[k] : expm1f(v[k]);

    if (dosplit) {
        float4 o0 = make_float4(to_tf32(v[0]), to_tf32(v[1]), to_tf32(v[2]), to_tf32(v[3]));
        float4 o1 = make_float4(to_tf32(v[4]), to_tf32(v[5]), to_tf32(v[6]), to_tf32(v[7]));
        *(float4*)(g_Af + (size_t)n * WID + c)     = o0;
        *(float4*)(g_Af + (size_t)n * WID + c + 4) = o1;
    } else {
        float4 w0 = *(const float4*)(linw + c), w1 = *(const float4*)(linw + c + 4);
        float part = v[0] * w0.x + v[1] * w0.y + v[2] * w0.z + v[3] * w0.w
                   + v[4] * w1.x + v[5] * w1.y + v[6] * w1.z + v[7] * w1.w;
#pragma unroll
        for (int o = 16; o; o >>= 1) part += __shfl_xor_sync(0xffffffffu, part, o);
        if (lane == 0) {
            int gg = g_i64flag ? (int)((const long long*)batch)[n]
                               : ((const int*)batch)[n];
            atomicAdd(&out[gg], part);
        }
    }
}

// ---------------- launch ----------------
extern "C" void kernel_launch(void* const* d_in, const int* in_sizes, int n_in,
                              void* d_out, int out_size) {
    const float* x     = (const float*)d_in[0];
    const void*  ei    = d_in[1];
    const void*  batch = d_in[3];
    const float* W[3]    = {(const float*)d_in[4],  (const float*)d_in[8],  (const float*)d_in[12]};
    const float* asrc[3] = {(const float*)d_in[5],  (const float*)d_in[9],  (const float*)d_in[13]};
    const float* adst[3] = {(const float*)d_in[6],  (const float*)d_in[10], (const float*)d_in[14]};
    const float* bb[3]   = {(const float*)d_in[7],  (const float*)d_in[11], (const float*)d_in[15]};
    const float* linw = (const float*)d_in[16];
    const float* linb = (const float*)d_in[17];
    float* out = (float*)d_out;

    static int smem_set = 0;
    if (!smem_set) {
        cudaFuncSetAttribute(k_gemm_mma, cudaFuncAttributeMaxDynamicSharedMemorySize, GSMEM3);
        smem_set = 1;
    }

    dim3 ggrid(MTILES, 2);
    int nodeGrid = (NNODES + 255) / 256;
    int aggGrid = NNODES / 4;   // 12500

    // probe + clear, layer-0 tf32 round (also zeroes g_als/ald), W0, GEMM0
    k_probe_clear<<<nodeGrid, 256>>>((const int*)ei);
    k_splitA<<<(NNODES * 128 / 4 + 255) / 256, 256>>>(x, NNODES * 128 / 4);
    k_splitW0<<<(128 * WID + 255) / 256, 256>>>(W[0], 128);
    k_gemm_mma<<<ggrid, 256, GSMEM3>>>(128, asrc[0], adst[0]);

    // bucket CSR build (single kernel; needed before first aggregate)
    k_count<<<(ETOT + 255) / 256, 256>>>(ei);

    // layer 0 tail
    k_aggregate<<<aggGrid, 128>>>(bb[0], 1, nullptr, nullptr, nullptr);

    // layer 1 (K=256); splitW also clears g_als/ald
    k_splitW<<<(256 * WID + 255) / 256, 256>>>(W[1], 256, nullptr, nullptr);
    k_gemm_mma<<<ggrid, 256, GSMEM3>>>(256, asrc[1], adst[1]);
    k_aggregate<<<aggGrid, 128>>>(bb[1], 1, nullptr, nullptr, nullptr);

    // layer 2 (K=256): splitW also inits out; aggregate fuses pooling + head
    k_splitW<<<(256 * WID + 255) / 256, 256>>>(W[2], 256, out, linb);
    k_gemm_mma<<<ggrid, 256, GSMEM3>>>(256, asrc[2], adst[2]);
    k_aggregate<<<aggGrid, 128>>>(bb[2], 0, linw, batch, out);
}